// round 14
// baseline (speedup 1.0000x reference)
#include <cuda_runtime.h>
#include <cuda_bf16.h>
#include <stdint.h>

// C = tril(tril(A) @ tril(B)), N=4096 fp32.
// R11: persistent CTAs + dynamic ticket (LPT), cp.async stream pipelined ACROSS
// sections (3-stage, never drains); mma.sync m16n8k16, 3-pass bf16 split.

#define BS 128
#define BK 32
#define TCH 16
#define APAD 40
#define BPAD 136

#define AHI_OFF 0
#define ALO_OFF (128 * APAD * 2)                 // 10240
#define BHI_OFF (ALO_OFF * 2)                    // 20480
#define BLO_OFF (BHI_OFF + BK * BPAD * 2)        // 29184
#define STAGE_BYTES (BLO_OFF + BK * BPAD * 2)    // 37888
#define NSTAGE 3

#define NMAX 4096ULL
__device__ __align__(16) __nv_bfloat16 gAhi[NMAX * NMAX];
__device__ __align__(16) __nv_bfloat16 gAlo[NMAX * NMAX];
__device__ __align__(16) __nv_bfloat16 gBhi[NMAX * NMAX];
__device__ __align__(16) __nv_bfloat16 gBlo[NMAX * NMAX];
__device__ int gTicket;

// ---------------- helpers ----------------
__device__ __forceinline__ uint32_t smem_u32(const void* p) {
    uint32_t a;
    asm("{ .reg .u64 t; cvta.to.shared.u64 t, %1; cvt.u32.u64 %0, t; }"
        : "=r"(a) : "l"(p));
    return a;
}
__device__ __forceinline__ uint32_t pack2(float a, float b) {
    __nv_bfloat162 v = __floats2bfloat162_rn(a, b);
    return *reinterpret_cast<uint32_t*>(&v);
}
__device__ __forceinline__ void splitf(float x, float& h, float& l) {
    __nv_bfloat16 bh = __float2bfloat16(x);
    h = __bfloat162float(bh);
    l = x - h;
}
__device__ __forceinline__ void ldsm4(uint32_t* r, uint32_t addr) {
    asm volatile("ldmatrix.sync.aligned.m8n8.x4.shared.b16 {%0,%1,%2,%3}, [%4];"
                 : "=r"(r[0]), "=r"(r[1]), "=r"(r[2]), "=r"(r[3]) : "r"(addr));
}
__device__ __forceinline__ void ldsm4t(uint32_t* r, uint32_t addr) {
    asm volatile("ldmatrix.sync.aligned.m8n8.x4.trans.shared.b16 {%0,%1,%2,%3}, [%4];"
                 : "=r"(r[0]), "=r"(r[1]), "=r"(r[2]), "=r"(r[3]) : "r"(addr));
}
__device__ __forceinline__ void mma16816(float* c, const uint32_t* a, const uint32_t* b) {
    asm volatile(
        "mma.sync.aligned.m16n8k16.row.col.f32.bf16.bf16.f32 "
        "{%0,%1,%2,%3}, {%4,%5,%6,%7}, {%8,%9}, {%0,%1,%2,%3};"
        : "+f"(c[0]), "+f"(c[1]), "+f"(c[2]), "+f"(c[3])
        : "r"(a[0]), "r"(a[1]), "r"(a[2]), "r"(a[3]), "r"(b[0]), "r"(b[1]));
}
__device__ __forceinline__ void cp16(uint32_t dst, const void* src) {
    asm volatile("cp.async.cg.shared.global [%0], [%1], 16;"
                 :: "r"(dst), "l"(__cvta_generic_to_global(src)) : "memory");
}
__device__ __forceinline__ void cp_commit() {
    asm volatile("cp.async.commit_group;" ::: "memory");
}
template<int n> __device__ __forceinline__ void cp_wait() {
    asm volatile("cp.async.wait_group %0;" :: "n"(n) : "memory");
}

// ------- fused: zero C + reset ticket + fp32 -> tril-masked bf16 hi/lo -------
__global__ __launch_bounds__(256)
void prepass_fused(const float* __restrict__ A, const float* __restrict__ B,
                   float* __restrict__ C, int N)
{
    if (blockIdx.x == 0 && threadIdx.x == 0) gTicket = 0;

    const size_t per = (size_t)N * N / 8;
    const size_t zgrp = (size_t)N * N / 4;
    size_t id = (size_t)blockIdx.x * 256 + threadIdx.x;

    if (id >= 2 * per) {
        size_t z = id - 2 * per;
        if (z < zgrp)
            reinterpret_cast<float4*>(C)[z] = make_float4(0.f, 0.f, 0.f, 0.f);
        return;
    }

    const bool isA = id < per;
    size_t e = (isA ? id : id - per) * 8;
    const int row = (int)(e / (size_t)N);
    const int col = (int)(e % (size_t)N);

    const float* S = isA ? A : B;
    __nv_bfloat16* dh = isA ? gAhi : gBhi;
    __nv_bfloat16* dl = isA ? gAlo : gBlo;

    float4 v0 = *reinterpret_cast<const float4*>(S + e);
    float4 v1 = *reinterpret_cast<const float4*>(S + e + 4);
    float f[8] = {v0.x, v0.y, v0.z, v0.w, v1.x, v1.y, v1.z, v1.w};

    uint32_t hp[4], lp[4];
    #pragma unroll
    for (int j = 0; j < 8; j += 2) {
        float x0 = (col + j     > row) ? 0.f : f[j];
        float x1 = (col + j + 1 > row) ? 0.f : f[j + 1];
        float h0, l0, h1, l1;
        splitf(x0, h0, l0);
        splitf(x1, h1, l1);
        hp[j >> 1] = pack2(h0, h1);
        lp[j >> 1] = pack2(l0, l1);
    }
    *reinterpret_cast<uint4*>(dh + e) = make_uint4(hp[0], hp[1], hp[2], hp[3]);
    *reinterpret_cast<uint4*>(dl + e) = make_uint4(lp[0], lp[1], lp[2], lp[3]);
}

// ---------------- section descriptor ----------------
struct Sec { int row0, col0, kBeg, nch, nsec, valid; };

__device__ __forceinline__ Sec decode_sec(int s, int nb, int total)
{
    Sec S;
    if (s >= total) { S.valid = 0; S.nch = 0; S.row0 = S.col0 = S.kBeg = 0; S.nsec = 1; return S; }
    int d, t = s, nsec = 1;
    for (d = nb - 1; d >= 0; d--) {
        nsec = 1 + (d >> 2);
        int cnt = (nb - d) * nsec;
        if (t < cnt) break;
        t -= cnt;
    }
    const int bj = t / nsec, sec = t % nsec, bi = bj + d;
    S.row0 = bi * BS;
    S.col0 = bj * BS;
    S.kBeg = bj * BS + sec * TCH * BK;
    S.nch  = min(TCH, 4 * (d + 1) - sec * TCH);
    S.nsec = nsec;
    S.valid = 1;
    return S;
}

// ---------------- main GEMM (persistent, cross-section pipeline) ----------------
__global__ __launch_bounds__(256, 2)
void trilmm_mma_kernel(float* __restrict__ C, int N, int nb, int total)
{
    extern __shared__ char smem[];
    __shared__ int sh_tix;
    const int tid = threadIdx.x;
    const int lane = tid & 31;
    const int wid  = tid >> 5;
    const int wm   = wid >> 2;
    const int wn   = wid & 3;

    const uint32_t sb = smem_u32(smem);

    // fragment offsets (section-independent)
    uint32_t a_off[4];
    #pragma unroll
    for (int mt = 0; mt < 4; mt++)
        a_off[mt] = (uint32_t)(((wm * 64 + mt * 16 + (lane & 15)) * APAD
                                + (lane >> 4) * 8) * 2);
    uint32_t b_off[2];
    #pragma unroll
    for (int p = 0; p < 2; p++)
        b_off[p] = (uint32_t)(((lane & 15) * BPAD
                               + wn * 32 + p * 16 + (lane >> 4) * 8) * 2);

    const int aRow = tid >> 2, aSeg = (tid & 3) * 8;
    const int bRow = tid >> 4, bSeg = (tid & 15) * 8;

    auto issue = [&](const Sec& S, int c, int slot) {
        const uint32_t base = sb + (uint32_t)slot * STAGE_BYTES;
        const int k0 = S.kBeg + c * BK;
        #pragma unroll
        for (int i = 0; i < 2; i++) {
            const int r = aRow + i * 64;
            const size_t g = (size_t)(S.row0 + r) * N + k0 + aSeg;
            const uint32_t dst = base + AHI_OFF + (uint32_t)((r * APAD + aSeg) * 2);
            cp16(dst, gAhi + g);
            cp16(dst + (ALO_OFF - AHI_OFF), gAlo + g);
        }
        #pragma unroll
        for (int i = 0; i < 2; i++) {
            const int r = bRow + i * 16;
            const size_t g = (size_t)(k0 + r) * N + S.col0 + bSeg;
            const uint32_t dst = base + BHI_OFF + (uint32_t)((r * BPAD + bSeg) * 2);
            cp16(dst, gBhi + g);
            cp16(dst + (BLO_OFF - BHI_OFF), gBlo + g);
        }
        cp_commit();
    };

    auto fetch = [&]() -> int {
        __syncthreads();
        if (tid == 0) sh_tix = atomicAdd(&gTicket, 1);
        __syncthreads();
        return sh_tix;
    };

    Sec cur = decode_sec(fetch(), nb, total);
    Sec nxt = decode_sec(fetch(), nb, total);
    if (!cur.valid) return;

    // prologue: first two chunks of the stream (cur.nch >= 4 always)
    issue(cur, 0, 0);
    issue(cur, 1, 1);
    int phase = 0;   // stage slot of the chunk about to be consumed

    while (cur.valid) {
        float acc[4][4][4];
        #pragma unroll
        for (int i = 0; i < 4; i++)
            #pragma unroll
            for (int j = 0; j < 4; j++)
                #pragma unroll
                for (int e = 0; e < 4; e++)
                    acc[i][j][e] = 0.f;

        const int nch = cur.nch;
        for (int c = 0; c < nch; c++) {
            cp_wait<1>();
            __syncthreads();

            // keep the stream 2 chunks ahead (may cross into next section)
            {
                const int slot = (phase + 2 >= NSTAGE) ? phase + 2 - NSTAGE : phase + 2;
                const int q2 = c + 2;
                if (q2 < nch)                                    issue(cur, q2, slot);
                else if (nxt.valid && q2 - nch < nxt.nch)        issue(nxt, q2 - nch, slot);
                else                                             cp_commit();   // empty pad group
            }

            const uint32_t stB = sb + (uint32_t)phase * STAGE_BYTES;
            const uint32_t aHiB = stB + AHI_OFF, aLoB = stB + ALO_OFF;
            const uint32_t bHiB = stB + BHI_OFF, bLoB = stB + BLO_OFF;

            #pragma unroll
            for (int ks = 0; ks < 2; ks++) {
                uint32_t af[4][4], bh[2][4], bl[2][4];
                #pragma unroll
                for (int mt = 0; mt < 4; mt++)
                    ldsm4(af[mt], aHiB + a_off[mt] + ks * 32);
                #pragma unroll
                for (int p = 0; p < 2; p++) {
                    ldsm4t(bh[p], bHiB + b_off[p] + ks * (16 * BPAD * 2));
                    ldsm4t(bl[p], bLoB + b_off[p] + ks * (16 * BPAD * 2));
                }
                #pragma unroll
                for (int mt = 0; mt < 4; mt++)
                    #pragma unroll
                    for (int nt = 0; nt < 4; nt++)
                        mma16816(acc[mt][nt], af[mt], &bh[nt >> 1][(nt & 1) * 2]);
                #pragma unroll
                for (int mt = 0; mt < 4; mt++)
                    #pragma unroll
                    for (int nt = 0; nt < 4; nt++)
                        mma16816(acc[mt][nt], af[mt], &bl[nt >> 1][(nt & 1) * 2]);
                #pragma unroll
                for (int mt = 0; mt < 4; mt++)
                    ldsm4(af[mt], aLoB + a_off[mt] + ks * 32);
                #pragma unroll
                for (int mt = 0; mt < 4; mt++)
                    #pragma unroll
                    for (int nt = 0; nt < 4; nt++)
                        mma16816(acc[mt][nt], af[mt], &bh[nt >> 1][(nt & 1) * 2]);
            }

            phase = (phase + 1 >= NSTAGE) ? phase + 1 - NSTAGE : phase + 1;
        }

        // ---- epilogue (loads for next section already in flight) ----
        if (cur.nsec == 1) {
            #pragma unroll
            for (int mt = 0; mt < 4; mt++) {
                #pragma unroll
                for (int nt = 0; nt < 4; nt++) {
                    const int r  = cur.row0 + wm * 64 + mt * 16 + (lane >> 2);
                    const int cb = cur.col0 + wn * 32 + nt * 8 + (lane & 3) * 2;
                    float2 v0 = make_float2(acc[mt][nt][0], acc[mt][nt][1]);
                    float2 v1 = make_float2(acc[mt][nt][2], acc[mt][nt][3]);
                    *reinterpret_cast<float2*>(&C[(size_t)r * N + cb])       = v0;
                    *reinterpret_cast<float2*>(&C[(size_t)(r + 8) * N + cb]) = v1;
                }
            }
        } else {
            #pragma unroll
            for (int mt = 0; mt < 4; mt++) {
                #pragma unroll
                for (int nt = 0; nt < 4; nt++) {
                    const int r  = cur.row0 + wm * 64 + mt * 16 + (lane >> 2);
                    const int cb = cur.col0 + wn * 32 + nt * 8 + (lane & 3) * 2;
                    atomicAdd(&C[(size_t)r * N + cb],           acc[mt][nt][0]);
                    atomicAdd(&C[(size_t)r * N + cb + 1],       acc[mt][nt][1]);
                    atomicAdd(&C[(size_t)(r + 8) * N + cb],     acc[mt][nt][2]);
                    atomicAdd(&C[(size_t)(r + 8) * N + cb + 1], acc[mt][nt][3]);
                }
            }
        }

        cur = nxt;
        nxt = decode_sec(fetch(), nb, total);
    }
}

// ---------------- launch ----------------
extern "C" void kernel_launch(void* const* d_in, const int* in_sizes, int n_in,
                              void* d_out, int out_size)
{
    const float* A = (const float*)d_in[0];
    const float* B = (const float*)d_in[1];
    float* C = (float*)d_out;

    int N = 1;
    {
        long long total = in_sizes[0];
        int lo = 1, hi = 65536;
        while (lo < hi) {
            int mid = (lo + hi) >> 1;
            if ((long long)mid * mid < total) lo = mid + 1; else hi = mid;
        }
        N = lo;
    }
    const int nb = N / BS;

    // fused zero + ticket reset + split prepass
    {
        long long work = 2LL * N * N / 8 + (long long)N * N / 4;
        prepass_fused<<<(int)((work + 255) / 256), 256>>>(A, B, C, N);
    }

    int totalSections = 0;
    for (int d = 0; d < nb; d++)
        totalSections += (nb - d) * (1 + (d >> 2));

    int sms = 148;
    cudaDeviceGetAttribute(&sms, cudaDevAttrMultiProcessorCount, 0);
    int grid = 2 * sms;
    if (grid > totalSections) grid = totalSections;

    cudaFuncSetAttribute(trilmm_mma_kernel,
                         cudaFuncAttributeMaxDynamicSharedMemorySize,
                         STAGE_BYTES * NSTAGE);
    trilmm_mma_kernel<<<grid, 256, STAGE_BYTES * NSTAGE>>>(C, N, nb, totalSections);
}